// round 5
// baseline (speedup 1.0000x reference)
#include <cuda_runtime.h>
#include <cstdint>

#define NN 50000
#define EE 400000
#define INF_ 256
#define OUTF 64
#define EDF 64
#define HH 4
#define HOUT 256   // H*OUT

// ---------------- device scratch (static, no allocs) ----------------
__device__ float g_W2[INF_ * HOUT];      // W_fc transposed: [i][h*64+o]
__device__ float g_Wi2[HOUT];
__device__ float g_Wj2[HOUT];
__device__ float g_v[HH * EDF];          // W_eatt[h] @ We[h]
__device__ float g_catt[HH];             // b_att + b_eatt . We
__device__ float g_z[(size_t)NN * HOUT]; // z[n][h*64+o]
__device__ float g_ai[NN * HH];
__device__ float g_aj[NN * HH];
__device__ float g_ex[(size_t)EE * HH];  // exp(logit) [e][h], later normalized alpha
__device__ float g_s[(size_t)NN * HH * EDF]; // gathered alpha-weighted edge_attr
// CSR
__device__ int g_deg[NN];
__device__ int g_off[NN + 1];
__device__ int g_cur[NN];
__device__ int g_bsum[256];
__device__ int g_csr_src[EE];
__device__ int g_csr_eid[EE];

// ---------------- K0: init + tiny precomputes ----------------
__global__ void __launch_bounds__(256) k_init(
    const float* __restrict__ W_fc, const float* __restrict__ W_att,
    const float* __restrict__ b_att, const float* __restrict__ W_eatt,
    const float* __restrict__ b_eatt)
{
    int idx = blockIdx.x * 256 + threadIdx.x;   // 0 .. 65535
    if (idx < NN) g_deg[idx] = 0;
    if (idx < INF_ * HOUT) {
        int i = idx / HOUT, c = idx % HOUT;
        int h = c / OUTF, o = c % OUTF;
        g_W2[i * HOUT + c] = W_fc[((size_t)h * INF_ + i) * OUTF + o];
    }
    if (idx < HOUT) {
        int h = idx / OUTF, o = idx % OUTF;
        g_Wi2[idx] = W_att[h * 192 + o];
        g_Wj2[idx] = W_att[h * 192 + 64 + o];
    }
    if (idx < HH * EDF) {
        int h = idx / EDF, f = idx % EDF;
        float s = 0.0f;
        #pragma unroll 8
        for (int g = 0; g < EDF; g++)
            s += W_eatt[((size_t)h * EDF + f) * EDF + g] * W_att[h * 192 + 128 + g];
        g_v[idx] = s;
    }
    if (idx < HH) {
        int h = idx;
        float s = b_att[h];
        for (int g = 0; g < EDF; g++)
            s += b_eatt[h * EDF + g] * W_att[h * 192 + 128 + g];
        g_catt[h] = s;
    }
}

// ---------------- K1: node GEMM z = x @ W2 + b, fused ai/aj dots ----------------
__global__ void __launch_bounds__(256) k_node_gemm(
    const float* __restrict__ x, const float* __restrict__ b_fc)
{
    __shared__ __align__(16) float As[64 * 20];
    __shared__ __align__(16) float Bs[16 * 64];
    const int head = blockIdx.y;
    const int rowbase = blockIdx.x * 64;
    const int colbase = head * 64;
    const int tid = threadIdx.x;
    const int tx = tid & 15, ty = tid >> 4;

    float c[4][4];
    #pragma unroll
    for (int i = 0; i < 4; i++)
        #pragma unroll
        for (int j = 0; j < 4; j++) c[i][j] = 0.0f;

    const int lr = tid >> 2;
    const int lq = (tid & 3) * 4;
    const int bk = tid >> 4;
    const int bn = (tid & 15) * 4;

    for (int kb = 0; kb < INF_; kb += 16) {
        float4 av = make_float4(0.f, 0.f, 0.f, 0.f);
        int arow = rowbase + lr;
        if (arow < NN) av = *(const float4*)(x + (size_t)arow * INF_ + kb + lq);
        *(float4*)(As + lr * 20 + lq) = av;
        float4 bv = *(const float4*)(g_W2 + (size_t)(kb + bk) * HOUT + colbase + bn);
        *(float4*)(Bs + bk * 64 + bn) = bv;
        __syncthreads();
        #pragma unroll
        for (int kk = 0; kk < 16; kk++) {
            float a0 = As[(ty * 4 + 0) * 20 + kk];
            float a1 = As[(ty * 4 + 1) * 20 + kk];
            float a2 = As[(ty * 4 + 2) * 20 + kk];
            float a3 = As[(ty * 4 + 3) * 20 + kk];
            float4 b = *(const float4*)(Bs + kk * 64 + tx * 4);
            c[0][0] += a0 * b.x; c[0][1] += a0 * b.y; c[0][2] += a0 * b.z; c[0][3] += a0 * b.w;
            c[1][0] += a1 * b.x; c[1][1] += a1 * b.y; c[1][2] += a1 * b.z; c[1][3] += a1 * b.w;
            c[2][0] += a2 * b.x; c[2][1] += a2 * b.y; c[2][2] += a2 * b.z; c[2][3] += a2 * b.w;
            c[3][0] += a3 * b.x; c[3][1] += a3 * b.y; c[3][2] += a3 * b.z; c[3][3] += a3 * b.w;
        }
        __syncthreads();
    }

    float4 bb = *(const float4*)(b_fc + colbase + tx * 4);
    float4 wi = *(const float4*)(g_Wi2 + colbase + tx * 4);
    float4 wj = *(const float4*)(g_Wj2 + colbase + tx * 4);

    #pragma unroll
    for (int i = 0; i < 4; i++) {
        int row = rowbase + ty * 4 + i;
        float4 r;
        r.x = c[i][0] + bb.x; r.y = c[i][1] + bb.y;
        r.z = c[i][2] + bb.z; r.w = c[i][3] + bb.w;
        float si = r.x * wi.x + r.y * wi.y + r.z * wi.z + r.w * wi.w;
        float sj = r.x * wj.x + r.y * wj.y + r.z * wj.z + r.w * wj.w;
        #pragma unroll
        for (int off = 8; off >= 1; off >>= 1) {
            si += __shfl_xor_sync(0xffffffffu, si, off);
            sj += __shfl_xor_sync(0xffffffffu, sj, off);
        }
        if (row < NN) {
            *(float4*)(g_z + (size_t)row * HOUT + colbase + tx * 4) = r;
            if (tx == 0) {
                g_ai[row * HH + head] = si;
                g_aj[row * HH + head] = sj;
            }
        }
    }
}

// ---------------- K2: edge logits + leaky relu + exp; fused degree histogram ----------------
__global__ void __launch_bounds__(128) k_edge_logits(
    const float* __restrict__ edge_attr, const int* __restrict__ ei)
{
    __shared__ float sm_ea[128 * 65];
    __shared__ float sm_v[HH * EDF];
    __shared__ float sm_c[HH];
    const int t = threadIdx.x;
    const int ebase = blockIdx.x * 128;

    #pragma unroll
    for (int j = 0; j < 16; j++) {
        int f4 = t + 128 * j;
        int eeI = f4 >> 4, qf = (f4 & 15) * 4;
        float4 v = *(const float4*)(edge_attr + (size_t)(ebase + eeI) * EDF + qf);
        float* p = sm_ea + eeI * 65 + qf;
        p[0] = v.x; p[1] = v.y; p[2] = v.z; p[3] = v.w;
    }
    if (t < HH * EDF) sm_v[t] = g_v[t];
    if (t + 128 < HH * EDF) sm_v[t + 128] = g_v[t + 128];
    if (t < HH) sm_c[t] = g_catt[t];
    __syncthreads();

    int ge = ebase + t;
    int src = ei[ge];
    int dst = ei[EE + ge];
    float4 ai4 = *(const float4*)(g_ai + dst * HH);
    float4 aj4 = *(const float4*)(g_aj + src * HH);
    float ain[4] = {ai4.x, ai4.y, ai4.z, ai4.w};
    float ajn[4] = {aj4.x, aj4.y, aj4.z, aj4.w};

    float exv[4];
    #pragma unroll
    for (int h = 0; h < HH; h++) {
        float acc = sm_c[h];
        #pragma unroll 16
        for (int f = 0; f < EDF; f++)
            acc += sm_ea[t * 65 + f] * sm_v[h * EDF + f];
        float a = acc + ain[h] + ajn[h];
        float e = (a > 0.0f) ? a : 0.2f * a;
        exv[h] = __expf(e);
    }
    *(float4*)(g_ex + (size_t)ge * 4) =
        make_float4(exv[0], exv[1], exv[2], exv[3]);
    atomicAdd(&g_deg[dst], 1);
}

// ---------------- CSR build: 3-stage scan + fill ----------------
__global__ void __launch_bounds__(256) k_scan_a()
{
    __shared__ int sh[256];
    int t = threadIdx.x;
    int idx = blockIdx.x * 256 + t;
    int v = (idx < NN) ? g_deg[idx] : 0;
    sh[t] = v;
    __syncthreads();
    #pragma unroll
    for (int d = 1; d < 256; d <<= 1) {
        int x = (t >= d) ? sh[t - d] : 0;
        __syncthreads();
        if (t >= d) sh[t] += x;
        __syncthreads();
    }
    if (idx < NN) g_off[idx] = sh[t] - v;       // exclusive within chunk
    if (t == 255) g_bsum[blockIdx.x] = sh[255]; // chunk total
}

__global__ void __launch_bounds__(256) k_scan_b(int nblocks)
{
    __shared__ int sh[256];
    int t = threadIdx.x;
    int v = (t < nblocks) ? g_bsum[t] : 0;
    sh[t] = v;
    __syncthreads();
    #pragma unroll
    for (int d = 1; d < 256; d <<= 1) {
        int x = (t >= d) ? sh[t - d] : 0;
        __syncthreads();
        if (t >= d) sh[t] += x;
        __syncthreads();
    }
    if (t < nblocks) g_bsum[t] = sh[t] - v;     // exclusive over chunk totals
}

__global__ void __launch_bounds__(256) k_scan_c()
{
    int idx = blockIdx.x * 256 + threadIdx.x;
    if (idx < NN) {
        int o = g_off[idx] + g_bsum[blockIdx.x];
        g_off[idx] = o;
        g_cur[idx] = o;
    }
    if (idx == 0) g_off[NN] = EE;
}

__global__ void __launch_bounds__(256) k_fill(const int* __restrict__ ei)
{
    int e = blockIdx.x * 256 + threadIdx.x;
    if (e >= EE) return;
    int src = ei[e];
    int dst = ei[EE + e];
    int pos = atomicAdd(&g_cur[dst], 1);
    g_csr_src[pos] = src;
    g_csr_eid[pos] = e;
}

// ---------------- K3: gather — softmax denom + out + s, no atomics ----------------
__global__ void __launch_bounds__(256) k_gather(
    const float* __restrict__ edge_attr, float* __restrict__ out)
{
    const int t = threadIdx.x;
    const int lane64 = t & 63;
    const int nl = t >> 6;
    const int n = blockIdx.x * 4 + nl;
    const int h = lane64 >> 4;
    const int q = lane64 & 15;

    const int beg = g_off[n];
    const int end = g_off[n + 1];

    // pass 1: per-(node,head) softmax denominator
    float ss = 0.0f;
    for (int i = beg + q; i < end; i += 16)
        ss += g_ex[(size_t)g_csr_eid[i] * 4 + h];
    #pragma unroll
    for (int o = 8; o >= 1; o >>= 1)
        ss += __shfl_xor_sync(0xffffffffu, ss, o, 16);
    float inv = 1.0f / ss;   // only used when end > beg

    // pass 2: gather messages
    float4 accO = make_float4(0.f, 0.f, 0.f, 0.f);
    float4 accS = make_float4(0.f, 0.f, 0.f, 0.f);
    for (int i = beg; i < end; i++) {
        int eid = g_csr_eid[i];
        int src = g_csr_src[i];
        float al = g_ex[(size_t)eid * 4 + h] * inv;
        if (q == 0) g_ex[(size_t)eid * 4 + h] = al;  // store normalized alpha
        float4 z4 = *(const float4*)(g_z + (size_t)src * HOUT + lane64 * 4);
        accO.x = fmaf(al, z4.x, accO.x);
        accO.y = fmaf(al, z4.y, accO.y);
        accO.z = fmaf(al, z4.z, accO.z);
        accO.w = fmaf(al, z4.w, accO.w);
        float4 e4 = *(const float4*)(edge_attr + (size_t)eid * EDF + q * 4);
        accS.x = fmaf(al, e4.x, accS.x);
        accS.y = fmaf(al, e4.y, accS.y);
        accS.z = fmaf(al, e4.z, accS.z);
        accS.w = fmaf(al, e4.w, accS.w);
    }
    *(float4*)(out + (size_t)n * HOUT + lane64 * 4) = accO;
    *(float4*)(g_s + (((size_t)n * HH + h) * EDF) + q * 4) = accS;
}

// ---------------- K4: transpose normalized alpha [e][h] -> [h][E] ----------------
__global__ void __launch_bounds__(256) k_alpha_t(float* __restrict__ alphaOut)
{
    int e = blockIdx.x * 256 + threadIdx.x;
    if (e >= EE) return;
    float4 a4 = *(const float4*)(g_ex + (size_t)e * 4);
    alphaOut[0 * (size_t)EE + e] = a4.x;
    alphaOut[1 * (size_t)EE + e] = a4.y;
    alphaOut[2 * (size_t)EE + e] = a4.z;
    alphaOut[3 * (size_t)EE + e] = a4.w;
}

// ---------------- K5: out += s @ W_edge + (deg>0 ? b_edge : 0) ----------------
__global__ void __launch_bounds__(256) k_out_gemm(
    const float* __restrict__ W_edge, const float* __restrict__ b_edge,
    float* __restrict__ out)
{
    __shared__ __align__(16) float As[64 * 68];
    __shared__ __align__(16) float Bs[64 * 64];
    const int h = blockIdx.y;
    const int rowbase = blockIdx.x * 64;
    const int tid = threadIdx.x;
    const int tx = tid & 15, ty = tid >> 4;

    {
        const int lr = tid >> 2;
        const int lq = (tid & 3) * 4;
        #pragma unroll
        for (int j = 0; j < 4; j++) {
            int f = lq + j * 16;
            int row = rowbase + lr;
            float4 v = make_float4(0.f, 0.f, 0.f, 0.f);
            if (row < NN)
                v = *(const float4*)(g_s + (((size_t)row * HH + h) * EDF) + f);
            *(float4*)(As + lr * 68 + f) = v;
        }
        const int fr = tid >> 4;
        const int qn = (tid & 15) * 4;
        #pragma unroll
        for (int j = 0; j < 4; j++) {
            int fk = fr + j * 16;
            float4 w = *(const float4*)(W_edge + ((size_t)h * EDF + fk) * OUTF + qn);
            *(float4*)(Bs + fk * 64 + qn) = w;
        }
    }
    __syncthreads();

    float c[4][4];
    #pragma unroll
    for (int i = 0; i < 4; i++)
        #pragma unroll
        for (int j = 0; j < 4; j++) c[i][j] = 0.0f;

    #pragma unroll 16
    for (int kk = 0; kk < EDF; kk++) {
        float a0 = As[(ty * 4 + 0) * 68 + kk];
        float a1 = As[(ty * 4 + 1) * 68 + kk];
        float a2 = As[(ty * 4 + 2) * 68 + kk];
        float a3 = As[(ty * 4 + 3) * 68 + kk];
        float4 b = *(const float4*)(Bs + kk * 64 + tx * 4);
        c[0][0] += a0 * b.x; c[0][1] += a0 * b.y; c[0][2] += a0 * b.z; c[0][3] += a0 * b.w;
        c[1][0] += a1 * b.x; c[1][1] += a1 * b.y; c[1][2] += a1 * b.z; c[1][3] += a1 * b.w;
        c[2][0] += a2 * b.x; c[2][1] += a2 * b.y; c[2][2] += a2 * b.z; c[2][3] += a2 * b.w;
        c[3][0] += a3 * b.x; c[3][1] += a3 * b.y; c[3][2] += a3 * b.z; c[3][3] += a3 * b.w;
    }

    float4 be = *(const float4*)(b_edge + h * OUTF + tx * 4);

    #pragma unroll
    for (int i = 0; i < 4; i++) {
        int row = rowbase + ty * 4 + i;
        if (row < NN) {
            float flag = (g_off[row + 1] - g_off[row]) > 0 ? 1.0f : 0.0f;
            float* po = out + (size_t)row * HOUT + h * OUTF + tx * 4;
            float4 o4 = *(const float4*)po;
            o4.x += c[i][0] + flag * be.x;
            o4.y += c[i][1] + flag * be.y;
            o4.z += c[i][2] + flag * be.z;
            o4.w += c[i][3] + flag * be.w;
            *(float4*)po = o4;
        }
    }
}

// ---------------- launch ----------------
extern "C" void kernel_launch(void* const* d_in, const int* in_sizes, int n_in,
                              void* d_out, int out_size)
{
    const float* x      = (const float*)d_in[0];
    const int*   ei     = (const int*)d_in[1];
    const float* eattr  = (const float*)d_in[2];
    const float* W_fc   = (const float*)d_in[3];
    const float* b_fc   = (const float*)d_in[4];
    const float* W_att  = (const float*)d_in[5];
    const float* b_att  = (const float*)d_in[6];
    const float* W_edge = (const float*)d_in[7];
    const float* b_edge = (const float*)d_in[8];
    const float* W_eatt = (const float*)d_in[9];
    const float* b_eatt = (const float*)d_in[10];
    float* out = (float*)d_out;
    float* alphaOut = out + (size_t)NN * HOUT;

    const int SCAN_BLKS = (NN + 255) / 256;  // 196

    k_init<<<256, 256>>>(W_fc, W_att, b_att, W_eatt, b_eatt);
    k_node_gemm<<<dim3((NN + 63) / 64, HH), 256>>>(x, b_fc);
    k_edge_logits<<<EE / 128, 128>>>(eattr, ei);
    k_scan_a<<<SCAN_BLKS, 256>>>();
    k_scan_b<<<1, 256>>>(SCAN_BLKS);
    k_scan_c<<<SCAN_BLKS, 256>>>();
    k_fill<<<(EE + 255) / 256, 256>>>(ei);
    k_gather<<<NN / 4, 256>>>(eattr, out);
    k_alpha_t<<<(EE + 255) / 256, 256>>>(alphaOut);
    k_out_gemm<<<dim3((NN + 63) / 64, HH), 256>>>(W_edge, b_edge, out);
}

// round 6
// speedup vs baseline: 1.0011x; 1.0011x over previous
#include <cuda_runtime.h>
#include <cstdint>

#define NN 50000
#define EE 400000
#define INF_ 256
#define OUTF 64
#define EDF 64
#define HH 4
#define HOUT 256   // H*OUT

// ---------------- device scratch (static, no allocs) ----------------
__device__ float g_W2[INF_ * HOUT];      // W_fc transposed: [i][h*64+o]
__device__ float g_Wi2[HOUT];
__device__ float g_Wj2[HOUT];
__device__ float g_v[HH * EDF];          // W_eatt[h] @ We[h]
__device__ float g_catt[HH];             // b_att + b_eatt . We
__device__ float g_z[(size_t)NN * HOUT]; // z[n][h*64+o]
__device__ float g_ai[NN * HH];
__device__ float g_aj[NN * HH];
__device__ float g_ex[(size_t)EE * HH];  // exp(logit) [e][h], later normalized alpha
__device__ float g_s[(size_t)NN * HH * EDF]; // gathered alpha-weighted edge_attr
// CSR
__device__ int g_deg[NN];
__device__ int g_off[NN + 1];
__device__ int g_cur[NN];
__device__ int g_bsum[256];
__device__ int g_csr_src[EE];
__device__ int g_csr_eid[EE];

// ---------------- K0: init + tiny precomputes ----------------
__global__ void __launch_bounds__(256) k_init(
    const float* __restrict__ W_fc, const float* __restrict__ W_att,
    const float* __restrict__ b_att, const float* __restrict__ W_eatt,
    const float* __restrict__ b_eatt)
{
    int idx = blockIdx.x * 256 + threadIdx.x;   // 0 .. 65535
    if (idx < NN) g_deg[idx] = 0;
    if (idx < INF_ * HOUT) {
        int i = idx / HOUT, c = idx % HOUT;
        int h = c / OUTF, o = c % OUTF;
        g_W2[i * HOUT + c] = W_fc[((size_t)h * INF_ + i) * OUTF + o];
    }
    if (idx < HOUT) {
        int h = idx / OUTF, o = idx % OUTF;
        g_Wi2[idx] = W_att[h * 192 + o];
        g_Wj2[idx] = W_att[h * 192 + 64 + o];
    }
    if (idx < HH * EDF) {
        int h = idx / EDF, f = idx % EDF;
        float s = 0.0f;
        #pragma unroll 8
        for (int g = 0; g < EDF; g++)
            s += W_eatt[((size_t)h * EDF + f) * EDF + g] * W_att[h * 192 + 128 + g];
        g_v[idx] = s;
    }
    if (idx < HH) {
        int h = idx;
        float s = b_att[h];
        for (int g = 0; g < EDF; g++)
            s += b_eatt[h * EDF + g] * W_att[h * 192 + 128 + g];
        g_catt[h] = s;
    }
}

// ---------------- K1: node GEMM z = x @ W2 + b, fused ai/aj dots ----------------
__global__ void __launch_bounds__(256) k_node_gemm(
    const float* __restrict__ x, const float* __restrict__ b_fc)
{
    __shared__ __align__(16) float As[64 * 20];
    __shared__ __align__(16) float Bs[16 * 64];
    const int head = blockIdx.y;
    const int rowbase = blockIdx.x * 64;
    const int colbase = head * 64;
    const int tid = threadIdx.x;
    const int tx = tid & 15, ty = tid >> 4;

    float c[4][4];
    #pragma unroll
    for (int i = 0; i < 4; i++)
        #pragma unroll
        for (int j = 0; j < 4; j++) c[i][j] = 0.0f;

    const int lr = tid >> 2;
    const int lq = (tid & 3) * 4;
    const int bk = tid >> 4;
    const int bn = (tid & 15) * 4;

    for (int kb = 0; kb < INF_; kb += 16) {
        float4 av = make_float4(0.f, 0.f, 0.f, 0.f);
        int arow = rowbase + lr;
        if (arow < NN) av = *(const float4*)(x + (size_t)arow * INF_ + kb + lq);
        *(float4*)(As + lr * 20 + lq) = av;
        float4 bv = *(const float4*)(g_W2 + (size_t)(kb + bk) * HOUT + colbase + bn);
        *(float4*)(Bs + bk * 64 + bn) = bv;
        __syncthreads();
        #pragma unroll
        for (int kk = 0; kk < 16; kk++) {
            float a0 = As[(ty * 4 + 0) * 20 + kk];
            float a1 = As[(ty * 4 + 1) * 20 + kk];
            float a2 = As[(ty * 4 + 2) * 20 + kk];
            float a3 = As[(ty * 4 + 3) * 20 + kk];
            float4 b = *(const float4*)(Bs + kk * 64 + tx * 4);
            c[0][0] += a0 * b.x; c[0][1] += a0 * b.y; c[0][2] += a0 * b.z; c[0][3] += a0 * b.w;
            c[1][0] += a1 * b.x; c[1][1] += a1 * b.y; c[1][2] += a1 * b.z; c[1][3] += a1 * b.w;
            c[2][0] += a2 * b.x; c[2][1] += a2 * b.y; c[2][2] += a2 * b.z; c[2][3] += a2 * b.w;
            c[3][0] += a3 * b.x; c[3][1] += a3 * b.y; c[3][2] += a3 * b.z; c[3][3] += a3 * b.w;
        }
        __syncthreads();
    }

    float4 bb = *(const float4*)(b_fc + colbase + tx * 4);
    float4 wi = *(const float4*)(g_Wi2 + colbase + tx * 4);
    float4 wj = *(const float4*)(g_Wj2 + colbase + tx * 4);

    #pragma unroll
    for (int i = 0; i < 4; i++) {
        int row = rowbase + ty * 4 + i;
        float4 r;
        r.x = c[i][0] + bb.x; r.y = c[i][1] + bb.y;
        r.z = c[i][2] + bb.z; r.w = c[i][3] + bb.w;
        float si = r.x * wi.x + r.y * wi.y + r.z * wi.z + r.w * wi.w;
        float sj = r.x * wj.x + r.y * wj.y + r.z * wj.z + r.w * wj.w;
        #pragma unroll
        for (int off = 8; off >= 1; off >>= 1) {
            si += __shfl_xor_sync(0xffffffffu, si, off);
            sj += __shfl_xor_sync(0xffffffffu, sj, off);
        }
        if (row < NN) {
            *(float4*)(g_z + (size_t)row * HOUT + colbase + tx * 4) = r;
            if (tx == 0) {
                g_ai[row * HH + head] = si;
                g_aj[row * HH + head] = sj;
            }
        }
    }
}

// ---------------- K2: edge logits + leaky relu + exp; fused degree histogram ----------------
__global__ void __launch_bounds__(128) k_edge_logits(
    const float* __restrict__ edge_attr, const int* __restrict__ ei)
{
    __shared__ float sm_ea[128 * 65];
    __shared__ float sm_v[HH * EDF];
    __shared__ float sm_c[HH];
    const int t = threadIdx.x;
    const int ebase = blockIdx.x * 128;

    #pragma unroll
    for (int j = 0; j < 16; j++) {
        int f4 = t + 128 * j;
        int eeI = f4 >> 4, qf = (f4 & 15) * 4;
        float4 v = *(const float4*)(edge_attr + (size_t)(ebase + eeI) * EDF + qf);
        float* p = sm_ea + eeI * 65 + qf;
        p[0] = v.x; p[1] = v.y; p[2] = v.z; p[3] = v.w;
    }
    if (t < HH * EDF) sm_v[t] = g_v[t];
    if (t + 128 < HH * EDF) sm_v[t + 128] = g_v[t + 128];
    if (t < HH) sm_c[t] = g_catt[t];
    __syncthreads();

    int ge = ebase + t;
    int src = ei[ge];
    int dst = ei[EE + ge];
    float4 ai4 = *(const float4*)(g_ai + dst * HH);
    float4 aj4 = *(const float4*)(g_aj + src * HH);
    float ain[4] = {ai4.x, ai4.y, ai4.z, ai4.w};
    float ajn[4] = {aj4.x, aj4.y, aj4.z, aj4.w};

    float exv[4];
    #pragma unroll
    for (int h = 0; h < HH; h++) {
        float acc = sm_c[h];
        #pragma unroll 16
        for (int f = 0; f < EDF; f++)
            acc += sm_ea[t * 65 + f] * sm_v[h * EDF + f];
        float a = acc + ain[h] + ajn[h];
        float e = (a > 0.0f) ? a : 0.2f * a;
        exv[h] = __expf(e);
    }
    *(float4*)(g_ex + (size_t)ge * 4) =
        make_float4(exv[0], exv[1], exv[2], exv[3]);
    atomicAdd(&g_deg[dst], 1);
}

// ---------------- CSR build: 3-stage scan + fill ----------------
__global__ void __launch_bounds__(256) k_scan_a()
{
    __shared__ int sh[256];
    int t = threadIdx.x;
    int idx = blockIdx.x * 256 + t;
    int v = (idx < NN) ? g_deg[idx] : 0;
    sh[t] = v;
    __syncthreads();
    #pragma unroll
    for (int d = 1; d < 256; d <<= 1) {
        int x = (t >= d) ? sh[t - d] : 0;
        __syncthreads();
        if (t >= d) sh[t] += x;
        __syncthreads();
    }
    if (idx < NN) g_off[idx] = sh[t] - v;       // exclusive within chunk
    if (t == 255) g_bsum[blockIdx.x] = sh[255]; // chunk total
}

__global__ void __launch_bounds__(256) k_scan_b(int nblocks)
{
    __shared__ int sh[256];
    int t = threadIdx.x;
    int v = (t < nblocks) ? g_bsum[t] : 0;
    sh[t] = v;
    __syncthreads();
    #pragma unroll
    for (int d = 1; d < 256; d <<= 1) {
        int x = (t >= d) ? sh[t - d] : 0;
        __syncthreads();
        if (t >= d) sh[t] += x;
        __syncthreads();
    }
    if (t < nblocks) g_bsum[t] = sh[t] - v;     // exclusive over chunk totals
}

__global__ void __launch_bounds__(256) k_scan_c()
{
    int idx = blockIdx.x * 256 + threadIdx.x;
    if (idx < NN) {
        int o = g_off[idx] + g_bsum[blockIdx.x];
        g_off[idx] = o;
        g_cur[idx] = o;
    }
    if (idx == 0) g_off[NN] = EE;
}

__global__ void __launch_bounds__(256) k_fill(const int* __restrict__ ei)
{
    int e = blockIdx.x * 256 + threadIdx.x;
    if (e >= EE) return;
    int src = ei[e];
    int dst = ei[EE + e];
    int pos = atomicAdd(&g_cur[dst], 1);
    g_csr_src[pos] = src;
    g_csr_eid[pos] = e;
}

// ---------------- K3: gather — softmax denom + out + s, no atomics ----------------
__global__ void __launch_bounds__(256) k_gather(
    const float* __restrict__ edge_attr, float* __restrict__ out)
{
    const int t = threadIdx.x;
    const int lane64 = t & 63;
    const int nl = t >> 6;
    const int n = blockIdx.x * 4 + nl;
    const int h = lane64 >> 4;
    const int q = lane64 & 15;

    const int beg = g_off[n];
    const int end = g_off[n + 1];

    // pass 1: per-(node,head) softmax denominator
    float ss = 0.0f;
    for (int i = beg + q; i < end; i += 16)
        ss += g_ex[(size_t)g_csr_eid[i] * 4 + h];
    #pragma unroll
    for (int o = 8; o >= 1; o >>= 1)
        ss += __shfl_xor_sync(0xffffffffu, ss, o, 16);
    float inv = 1.0f / ss;   // only used when end > beg

    // pass 2: gather messages
    float4 accO = make_float4(0.f, 0.f, 0.f, 0.f);
    float4 accS = make_float4(0.f, 0.f, 0.f, 0.f);
    for (int i = beg; i < end; i++) {
        int eid = g_csr_eid[i];
        int src = g_csr_src[i];
        float al = g_ex[(size_t)eid * 4 + h] * inv;
        if (q == 0) g_ex[(size_t)eid * 4 + h] = al;  // store normalized alpha
        float4 z4 = *(const float4*)(g_z + (size_t)src * HOUT + lane64 * 4);
        accO.x = fmaf(al, z4.x, accO.x);
        accO.y = fmaf(al, z4.y, accO.y);
        accO.z = fmaf(al, z4.z, accO.z);
        accO.w = fmaf(al, z4.w, accO.w);
        float4 e4 = *(const float4*)(edge_attr + (size_t)eid * EDF + q * 4);
        accS.x = fmaf(al, e4.x, accS.x);
        accS.y = fmaf(al, e4.y, accS.y);
        accS.z = fmaf(al, e4.z, accS.z);
        accS.w = fmaf(al, e4.w, accS.w);
    }
    *(float4*)(out + (size_t)n * HOUT + lane64 * 4) = accO;
    *(float4*)(g_s + (((size_t)n * HH + h) * EDF) + q * 4) = accS;
}

// ---------------- K4: transpose normalized alpha [e][h] -> [h][E] ----------------
__global__ void __launch_bounds__(256) k_alpha_t(float* __restrict__ alphaOut)
{
    int e = blockIdx.x * 256 + threadIdx.x;
    if (e >= EE) return;
    float4 a4 = *(const float4*)(g_ex + (size_t)e * 4);
    alphaOut[0 * (size_t)EE + e] = a4.x;
    alphaOut[1 * (size_t)EE + e] = a4.y;
    alphaOut[2 * (size_t)EE + e] = a4.z;
    alphaOut[3 * (size_t)EE + e] = a4.w;
}

// ---------------- K5: out += s @ W_edge + (deg>0 ? b_edge : 0) ----------------
__global__ void __launch_bounds__(256) k_out_gemm(
    const float* __restrict__ W_edge, const float* __restrict__ b_edge,
    float* __restrict__ out)
{
    __shared__ __align__(16) float As[64 * 68];
    __shared__ __align__(16) float Bs[64 * 64];
    const int h = blockIdx.y;
    const int rowbase = blockIdx.x * 64;
    const int tid = threadIdx.x;
    const int tx = tid & 15, ty = tid >> 4;

    {
        const int lr = tid >> 2;
        const int lq = (tid & 3) * 4;
        #pragma unroll
        for (int j = 0; j < 4; j++) {
            int f = lq + j * 16;
            int row = rowbase + lr;
            float4 v = make_float4(0.f, 0.f, 0.f, 0.f);
            if (row < NN)
                v = *(const float4*)(g_s + (((size_t)row * HH + h) * EDF) + f);
            *(float4*)(As + lr * 68 + f) = v;
        }
        const int fr = tid >> 4;
        const int qn = (tid & 15) * 4;
        #pragma unroll
        for (int j = 0; j < 4; j++) {
            int fk = fr + j * 16;
            float4 w = *(const float4*)(W_edge + ((size_t)h * EDF + fk) * OUTF + qn);
            *(float4*)(Bs + fk * 64 + qn) = w;
        }
    }
    __syncthreads();

    float c[4][4];
    #pragma unroll
    for (int i = 0; i < 4; i++)
        #pragma unroll
        for (int j = 0; j < 4; j++) c[i][j] = 0.0f;

    #pragma unroll 16
    for (int kk = 0; kk < EDF; kk++) {
        float a0 = As[(ty * 4 + 0) * 68 + kk];
        float a1 = As[(ty * 4 + 1) * 68 + kk];
        float a2 = As[(ty * 4 + 2) * 68 + kk];
        float a3 = As[(ty * 4 + 3) * 68 + kk];
        float4 b = *(const float4*)(Bs + kk * 64 + tx * 4);
        c[0][0] += a0 * b.x; c[0][1] += a0 * b.y; c[0][2] += a0 * b.z; c[0][3] += a0 * b.w;
        c[1][0] += a1 * b.x; c[1][1] += a1 * b.y; c[1][2] += a1 * b.z; c[1][3] += a1 * b.w;
        c[2][0] += a2 * b.x; c[2][1] += a2 * b.y; c[2][2] += a2 * b.z; c[2][3] += a2 * b.w;
        c[3][0] += a3 * b.x; c[3][1] += a3 * b.y; c[3][2] += a3 * b.z; c[3][3] += a3 * b.w;
    }

    float4 be = *(const float4*)(b_edge + h * OUTF + tx * 4);

    #pragma unroll
    for (int i = 0; i < 4; i++) {
        int row = rowbase + ty * 4 + i;
        if (row < NN) {
            float flag = (g_off[row + 1] - g_off[row]) > 0 ? 1.0f : 0.0f;
            float* po = out + (size_t)row * HOUT + h * OUTF + tx * 4;
            float4 o4 = *(const float4*)po;
            o4.x += c[i][0] + flag * be.x;
            o4.y += c[i][1] + flag * be.y;
            o4.z += c[i][2] + flag * be.z;
            o4.w += c[i][3] + flag * be.w;
            *(float4*)po = o4;
        }
    }
}

// ---------------- launch ----------------
extern "C" void kernel_launch(void* const* d_in, const int* in_sizes, int n_in,
                              void* d_out, int out_size)
{
    const float* x      = (const float*)d_in[0];
    const int*   ei     = (const int*)d_in[1];
    const float* eattr  = (const float*)d_in[2];
    const float* W_fc   = (const float*)d_in[3];
    const float* b_fc   = (const float*)d_in[4];
    const float* W_att  = (const float*)d_in[5];
    const float* b_att  = (const float*)d_in[6];
    const float* W_edge = (const float*)d_in[7];
    const float* b_edge = (const float*)d_in[8];
    const float* W_eatt = (const float*)d_in[9];
    const float* b_eatt = (const float*)d_in[10];
    float* out = (float*)d_out;
    float* alphaOut = out + (size_t)NN * HOUT;

    const int SCAN_BLKS = (NN + 255) / 256;  // 196

    k_init<<<256, 256>>>(W_fc, W_att, b_att, W_eatt, b_eatt);
    k_node_gemm<<<dim3((NN + 63) / 64, HH), 256>>>(x, b_fc);
    k_edge_logits<<<EE / 128, 128>>>(eattr, ei);
    k_scan_a<<<SCAN_BLKS, 256>>>();
    k_scan_b<<<1, 256>>>(SCAN_BLKS);
    k_scan_c<<<SCAN_BLKS, 256>>>();
    k_fill<<<(EE + 255) / 256, 256>>>(ei);
    k_gather<<<NN / 4, 256>>>(eattr, out);
    k_alpha_t<<<(EE + 255) / 256, 256>>>(alphaOut);
    k_out_gemm<<<dim3((NN + 63) / 64, HH), 256>>>(W_edge, b_edge, out);
}